// round 1
// baseline (speedup 1.0000x reference)
#include <cuda_runtime.h>

// Problem constants (fixed by the dataset)
#define BB   16
#define NN   32
#define HH   512
#define WW   512
#define CC   512
#define SS   256    // 16*16 pooled spatial
#define EE   128

// Scratch (static device globals — no runtime allocation)
__device__ float g_proj[BB * EE * SS];   // 2 MB: projected+BN+ReLU features [b][e][s]
__device__ float g_mr[BB * NN * SS];     // resized masks [bn][s]
__device__ float g_minv[BB * NN];        // 1/(mask_sum + eps)

// ---------------------------------------------------------------------------
// Kernel A: fused {proj GEMM + BN + ReLU} (blocks 0..255) and
//           {bilinear mask resize + sum} (blocks 256..767).
// 128 threads per block.
// GEMM tiling: block tile 64(E) x 32(S), K-tile 16, thread microtile 4x4.
// ---------------------------------------------------------------------------
__global__ void __launch_bounds__(128) kernelA(
    const float* __restrict__ features,   // [B, C, 16, 16]
    const float* __restrict__ masks,      // [B, N, 512, 512]
    const float* __restrict__ conv_w,     // [E, C]
    const float* __restrict__ conv_b,     // [E]
    const float* __restrict__ bn_gamma,
    const float* __restrict__ bn_beta,
    const float* __restrict__ bn_mean,
    const float* __restrict__ bn_var)
{
    __shared__ float sW[16 * 68];   // [k][e] transposed W tile, padded stride 68
    __shared__ float sF[16 * 36];   // [k][s] F tile, padded stride 36

    const int blk = blockIdx.x;
    const int tid = threadIdx.x;

    if (blk >= 256) {
        // ---------------- mask resize path ----------------
        const int bn = blk - 256;                 // 0..511
        const float* m = masks + (size_t)bn * (HH * WW);
        float lsum = 0.0f;

        #pragma unroll
        for (int rep = 0; rep < 2; rep++) {
            const int t = tid + rep * 128;        // pooled pixel 0..255
            const int o = t >> 4;                 // out row
            const int p = t & 15;                 // out col
            // torch bilinear (align_corners=False): src = max(0,(i+0.5)*scale-0.5)
            float sy = (o + 0.5f) * ((float)HH / 16.0f) - 0.5f;
            sy = fmaxf(sy, 0.0f);
            int   y0 = (int)floorf(sy);
            float fy = sy - (float)y0;
            int   y1 = min(y0 + 1, HH - 1);
            float sx = (p + 0.5f) * ((float)WW / 16.0f) - 0.5f;
            sx = fmaxf(sx, 0.0f);
            int   x0 = (int)floorf(sx);
            float fx = sx - (float)x0;
            int   x1 = min(x0 + 1, WW - 1);

            float v00 = m[(size_t)y0 * WW + x0];
            float v01 = m[(size_t)y0 * WW + x1];
            float v10 = m[(size_t)y1 * WW + x0];
            float v11 = m[(size_t)y1 * WW + x1];
            float v = (1.0f - fy) * ((1.0f - fx) * v00 + fx * v01)
                    +          fy * ((1.0f - fx) * v10 + fx * v11);

            g_mr[(size_t)bn * SS + t] = v;
            lsum += v;
        }
        // block reduction of lsum
        #pragma unroll
        for (int off = 16; off > 0; off >>= 1)
            lsum += __shfl_xor_sync(0xFFFFFFFFu, lsum, off);
        if ((tid & 31) == 0) sW[tid >> 5] = lsum;
        __syncthreads();
        if (tid == 0) {
            float s = sW[0] + sW[1] + sW[2] + sW[3];
            g_minv[bn] = 1.0f / (s + 1e-8f);
        }
        return;
    }

    // ---------------- GEMM path ----------------
    // blk = b*16 + et*8 + st : b in [0,16), et in {0,1} (E tile of 64), st in [0,8) (S tile of 32)
    const int b     = blk >> 4;
    const int et    = (blk >> 3) & 1;
    const int st    = blk & 7;
    const int eBase = et * 64;
    const int sBase = st * 32;

    const int te = tid >> 3;          // 0..15  -> e micro-row = te*4
    const int ts = tid & 7;           // 0..7   -> s micro-col = ts*4

    // global load assignments
    const int we = tid & 63;          // W row within tile
    const int wh = tid >> 6;          // 0/1 -> k-half (8 each)
    const int fk = tid >> 3;          // F k row 0..15
    const int fs = (tid & 7) << 2;    // F s col (x4)

    const float* wptr = conv_w + (size_t)(eBase + we) * CC + (wh << 3);
    const float* fptr = features + ((size_t)b * CC + fk) * SS + sBase + fs;

    float acc[4][4];
    #pragma unroll
    for (int i = 0; i < 4; i++)
        #pragma unroll
        for (int j = 0; j < 4; j++) acc[i][j] = 0.0f;

    // prefetch first K-tile
    float4 wr0 = *(const float4*)(wptr);
    float4 wr1 = *(const float4*)(wptr + 4);
    float4 fr  = *(const float4*)(fptr);

    for (int it = 0; it < 32; it++) {
        __syncthreads();   // previous compute done before overwriting smem
        {
            const int kk = wh << 3;
            sW[(kk + 0) * 68 + we] = wr0.x;
            sW[(kk + 1) * 68 + we] = wr0.y;
            sW[(kk + 2) * 68 + we] = wr0.z;
            sW[(kk + 3) * 68 + we] = wr0.w;
            sW[(kk + 4) * 68 + we] = wr1.x;
            sW[(kk + 5) * 68 + we] = wr1.y;
            sW[(kk + 6) * 68 + we] = wr1.z;
            sW[(kk + 7) * 68 + we] = wr1.w;
            *(float4*)&sF[fk * 36 + fs] = fr;
        }
        __syncthreads();

        if (it < 31) {   // prefetch next K-tile (latency hidden under compute)
            const int c0 = (it + 1) << 4;
            wr0 = *(const float4*)(wptr + c0);
            wr1 = *(const float4*)(wptr + c0 + 4);
            fr  = *(const float4*)(fptr + c0 * SS);
        }

        #pragma unroll
        for (int kk = 0; kk < 16; kk++) {
            float4 a = *(const float4*)&sW[kk * 68 + (te << 2)];
            float4 f = *(const float4*)&sF[kk * 36 + (ts << 2)];
            float av[4] = {a.x, a.y, a.z, a.w};
            float fv[4] = {f.x, f.y, f.z, f.w};
            #pragma unroll
            for (int i = 0; i < 4; i++)
                #pragma unroll
                for (int j = 0; j < 4; j++)
                    acc[i][j] += av[i] * fv[j];
        }
    }

    // epilogue: conv bias + BN (eval) + ReLU, fold into scale/bias per channel
    const int s0 = sBase + (ts << 2);
    #pragma unroll
    for (int i = 0; i < 4; i++) {
        const int e = eBase + (te << 2) + i;
        const float sc   = bn_gamma[e] * rsqrtf(bn_var[e] + 1e-5f);
        const float bias = (conv_b[e] - bn_mean[e]) * sc + bn_beta[e];
        float4 o;
        o.x = fmaxf(acc[i][0] * sc + bias, 0.0f);
        o.y = fmaxf(acc[i][1] * sc + bias, 0.0f);
        o.z = fmaxf(acc[i][2] * sc + bias, 0.0f);
        o.w = fmaxf(acc[i][3] * sc + bias, 0.0f);
        *(float4*)&g_proj[((size_t)(b * EE + e)) * SS + s0] = o;
    }
}

// ---------------------------------------------------------------------------
// Kernel B: mask-weighted pooling (obj) + 2-layer MLP, fused.
// Grid: 128 blocks = (b in [0,16)) x (ng in [0,8)); each block owns 4 (b,n) rows.
// 128 threads; thread tid = output channel e.
// ---------------------------------------------------------------------------
__global__ void __launch_bounds__(128) kernelB(
    const float* __restrict__ w1, const float* __restrict__ b1,
    const float* __restrict__ w2, const float* __restrict__ b2,
    float* __restrict__ out)
{
    const int b  = blockIdx.x >> 3;
    const int ng = blockIdx.x & 7;
    const int tid = threadIdx.x;

    __shared__ float mrs[4][SS];   // 4 resized masks
    __shared__ float xs[4][EE];    // obj rows
    __shared__ float hs[4][EE];    // hidden rows
    __shared__ float inv[4];

    const int n0 = ng * 4;
    for (int i = tid; i < 4 * SS; i += 128) {
        const int r = i >> 8;
        const int s = i & 255;
        mrs[r][s] = g_mr[((size_t)(b * NN + n0 + r)) * SS + s];
    }
    if (tid < 4) inv[tid] = g_minv[b * NN + n0 + tid];
    __syncthreads();

    // obj[r][e=tid] = inv[r] * sum_s proj[b][e][s] * mr[r][s]
    {
        float a0 = 0.f, a1 = 0.f, a2 = 0.f, a3 = 0.f;
        const float* pr = g_proj + ((size_t)(b * EE + tid)) * SS;
        #pragma unroll 4
        for (int s = 0; s < SS; s += 4) {
            float4 p4 = *(const float4*)&pr[s];
            float4 m0 = *(const float4*)&mrs[0][s];
            float4 m1 = *(const float4*)&mrs[1][s];
            float4 m2 = *(const float4*)&mrs[2][s];
            float4 m3 = *(const float4*)&mrs[3][s];
            a0 += p4.x * m0.x + p4.y * m0.y + p4.z * m0.z + p4.w * m0.w;
            a1 += p4.x * m1.x + p4.y * m1.y + p4.z * m1.z + p4.w * m1.w;
            a2 += p4.x * m2.x + p4.y * m2.y + p4.z * m2.z + p4.w * m2.w;
            a3 += p4.x * m3.x + p4.y * m3.y + p4.z * m3.z + p4.w * m3.w;
        }
        xs[0][tid] = a0 * inv[0];
        xs[1][tid] = a1 * inv[1];
        xs[2][tid] = a2 * inv[2];
        xs[3][tid] = a3 * inv[3];
    }
    __syncthreads();

    // layer 1: hdn[r][e] = relu(b1[e] + sum_k xs[r][k] * w1[e][k])
    {
        const float* wrow = w1 + (size_t)tid * EE;
        float a0 = 0.f, a1 = 0.f, a2 = 0.f, a3 = 0.f;
        #pragma unroll 8
        for (int k = 0; k < EE; k += 4) {
            float4 wv = *(const float4*)&wrow[k];
            float4 x0 = *(const float4*)&xs[0][k];
            float4 x1 = *(const float4*)&xs[1][k];
            float4 x2 = *(const float4*)&xs[2][k];
            float4 x3 = *(const float4*)&xs[3][k];
            a0 += wv.x * x0.x + wv.y * x0.y + wv.z * x0.z + wv.w * x0.w;
            a1 += wv.x * x1.x + wv.y * x1.y + wv.z * x1.z + wv.w * x1.w;
            a2 += wv.x * x2.x + wv.y * x2.y + wv.z * x2.z + wv.w * x2.w;
            a3 += wv.x * x3.x + wv.y * x3.y + wv.z * x3.z + wv.w * x3.w;
        }
        const float bb = b1[tid];
        hs[0][tid] = fmaxf(a0 + bb, 0.f);
        hs[1][tid] = fmaxf(a1 + bb, 0.f);
        hs[2][tid] = fmaxf(a2 + bb, 0.f);
        hs[3][tid] = fmaxf(a3 + bb, 0.f);
    }
    __syncthreads();

    // layer 2: out[r][e] = b2[e] + sum_k hs[r][k] * w2[e][k]
    {
        const float* wrow = w2 + (size_t)tid * EE;
        float a0 = 0.f, a1 = 0.f, a2 = 0.f, a3 = 0.f;
        #pragma unroll 8
        for (int k = 0; k < EE; k += 4) {
            float4 wv = *(const float4*)&wrow[k];
            float4 x0 = *(const float4*)&hs[0][k];
            float4 x1 = *(const float4*)&hs[1][k];
            float4 x2 = *(const float4*)&hs[2][k];
            float4 x3 = *(const float4*)&hs[3][k];
            a0 += wv.x * x0.x + wv.y * x0.y + wv.z * x0.z + wv.w * x0.w;
            a1 += wv.x * x1.x + wv.y * x1.y + wv.z * x1.z + wv.w * x1.w;
            a2 += wv.x * x2.x + wv.y * x2.y + wv.z * x2.z + wv.w * x2.w;
            a3 += wv.x * x3.x + wv.y * x3.y + wv.z * x3.z + wv.w * x3.w;
        }
        const float bb = b2[tid];
        out[((size_t)(b * NN + n0 + 0)) * EE + tid] = a0 + bb;
        out[((size_t)(b * NN + n0 + 1)) * EE + tid] = a1 + bb;
        out[((size_t)(b * NN + n0 + 2)) * EE + tid] = a2 + bb;
        out[((size_t)(b * NN + n0 + 3)) * EE + tid] = a3 + bb;
    }
}

extern "C" void kernel_launch(void* const* d_in, const int* in_sizes, int n_in,
                              void* d_out, int out_size)
{
    const float* features = (const float*)d_in[0];
    const float* masks    = (const float*)d_in[1];
    const float* conv_w   = (const float*)d_in[2];
    const float* conv_b   = (const float*)d_in[3];
    const float* bn_gamma = (const float*)d_in[4];
    const float* bn_beta  = (const float*)d_in[5];
    const float* bn_mean  = (const float*)d_in[6];
    const float* bn_var   = (const float*)d_in[7];
    const float* w1       = (const float*)d_in[8];
    const float* b1       = (const float*)d_in[9];
    const float* w2       = (const float*)d_in[10];
    const float* b2       = (const float*)d_in[11];
    float* out = (float*)d_out;

    kernelA<<<768, 128>>>(features, masks, conv_w, conv_b,
                          bn_gamma, bn_beta, bn_mean, bn_var);
    kernelB<<<128, 128>>>(w1, b1, w2, b2, out);
}

// round 2
// speedup vs baseline: 1.1027x; 1.1027x over previous
#include <cuda_runtime.h>

// Problem constants (fixed by the dataset)
#define BB   16
#define NN   32
#define HH   512
#define WW   512
#define CC   512
#define SS   256    // 16*16 pooled spatial
#define EE   128

// Scratch (static device globals — no runtime allocation)
__device__ float g_proj[BB * EE * SS];   // 2 MB: raw GEMM sums [b][e][s] (BN/ReLU applied in kernelB)
__device__ float g_mr[BB * NN * SS];     // resized masks [bn][s]
__device__ float g_minv[BB * NN];        // 1/(mask_sum + eps)

// ---------------------------------------------------------------------------
// Zero kernel: clear the split-K accumulation buffer.
// 128 blocks x 1024 threads x float4 = 524288 floats exactly.
// ---------------------------------------------------------------------------
__global__ void __launch_bounds__(1024) kernelZero()
{
    const int i = (blockIdx.x * 1024 + threadIdx.x) * 4;
    *(float4*)&g_proj[i] = make_float4(0.f, 0.f, 0.f, 0.f);
}

// ---------------------------------------------------------------------------
// Kernel A:
//   blocks [0,512):    split-K GEMM.  out[e][b*256+s] = sum_c W[e][c]*F[b][c][s]
//                      One big M=128 x N=4096 x K=512 GEMM (W shared across b),
//                      block tile 64E x 64S x 128K (split-K=4), 128 threads,
//                      microtile 8E x 4S, double-buffered smem, REDG epilogue.
//   blocks [512,1024): bilinear mask resize (512->16) + mask sums.
// ---------------------------------------------------------------------------
__global__ void __launch_bounds__(128) kernelA(
    const float* __restrict__ features,   // [B, C, 16, 16]
    const float* __restrict__ masks,      // [B, N, 512, 512]
    const float* __restrict__ conv_w)     // [E, C]
{
    __shared__ float sW[2][8][68];
    __shared__ float sF[2][8][68];
    __shared__ float red[4];

    const int blk = blockIdx.x;
    const int tid = threadIdx.x;

    if (blk >= 512) {
        // ---------------- mask resize path ----------------
        const int bn = blk - 512;                 // 0..511
        const float* m = masks + (size_t)bn * (HH * WW);
        float lsum = 0.0f;

        #pragma unroll
        for (int rep = 0; rep < 2; rep++) {
            const int t = tid + rep * 128;        // pooled pixel 0..255
            const int o = t >> 4;                 // out row
            const int p = t & 15;                 // out col
            // torch bilinear (align_corners=False): src = max(0,(i+0.5)*scale-0.5)
            float sy = (o + 0.5f) * ((float)HH / 16.0f) - 0.5f;
            sy = fmaxf(sy, 0.0f);
            int   y0 = (int)floorf(sy);
            float fy = sy - (float)y0;
            int   y1 = min(y0 + 1, HH - 1);
            float sx = (p + 0.5f) * ((float)WW / 16.0f) - 0.5f;
            sx = fmaxf(sx, 0.0f);
            int   x0 = (int)floorf(sx);
            float fx = sx - (float)x0;
            int   x1 = min(x0 + 1, WW - 1);

            float v00 = m[(size_t)y0 * WW + x0];
            float v01 = m[(size_t)y0 * WW + x1];
            float v10 = m[(size_t)y1 * WW + x0];
            float v11 = m[(size_t)y1 * WW + x1];
            float v = (1.0f - fy) * ((1.0f - fx) * v00 + fx * v01)
                    +          fy * ((1.0f - fx) * v10 + fx * v11);

            g_mr[(size_t)bn * SS + t] = v;
            lsum += v;
        }
        #pragma unroll
        for (int off = 16; off > 0; off >>= 1)
            lsum += __shfl_xor_sync(0xFFFFFFFFu, lsum, off);
        if ((tid & 31) == 0) red[tid >> 5] = lsum;
        __syncthreads();
        if (tid == 0) {
            float s = red[0] + red[1] + red[2] + red[3];
            g_minv[bn] = 1.0f / (s + 1e-8f);
        }
        return;
    }

    // ---------------- GEMM path ----------------
    // blk = kc*128 + et*64 + stile ; kc: K-chunk of 128, et: E tile of 64,
    // stile: 64-wide S tile within the flattened 4096-column dimension.
    const int kc    = blk >> 7;           // 0..3
    const int r     = blk & 127;
    const int et    = r >> 6;             // 0..1
    const int stile = r & 63;             // 0..63
    const int b     = stile >> 2;         // batch
    const int s0    = (stile & 3) * 64;   // s offset within batch
    const int eBase = et * 64;
    const int c0    = kc * 128;

    // microtile: 8 E x 4 S per thread
    const int te = tid >> 4;              // 0..7  -> e = te*8
    const int ts = tid & 15;              // 0..15 -> s = ts*4

    // global load roles
    const int we = tid & 63;              // W row (e) within tile
    const int wk = tid >> 6;              // 0..1  -> 4 k values each
    const int fk = tid >> 4;              // 0..7  -> F k row
    const int fs = (tid & 15) << 2;       // F s col

    const float* wp = conv_w + (size_t)(eBase + we) * CC + c0 + (wk << 2);
    const float* fp = features + ((size_t)b * CC + c0 + fk) * SS + s0 + fs;

    float acc[8][4];
    #pragma unroll
    for (int i = 0; i < 8; i++)
        #pragma unroll
        for (int j = 0; j < 4; j++) acc[i][j] = 0.0f;

    // prefetch tile 0
    float4 wr = *(const float4*)wp;   wp += 8;
    float4 fr = *(const float4*)fp;   fp += 8 * SS;

    // store tile 0 into buffer 0
    {
        const int kk = wk << 2;
        sW[0][kk + 0][we] = wr.x;
        sW[0][kk + 1][we] = wr.y;
        sW[0][kk + 2][we] = wr.z;
        sW[0][kk + 3][we] = wr.w;
        *(float4*)&sF[0][fk][fs] = fr;
    }
    __syncthreads();

    #pragma unroll 1
    for (int t = 0; t < 16; t++) {
        const int cur = t & 1;
        if (t < 15) {                       // prefetch next tile
            wr = *(const float4*)wp;  wp += 8;
            fr = *(const float4*)fp;  fp += 8 * SS;
        }
        #pragma unroll
        for (int k = 0; k < 8; k++) {
            float4 a0 = *(const float4*)&sW[cur][k][te << 3];
            float4 a1 = *(const float4*)&sW[cur][k][(te << 3) + 4];
            float4 f  = *(const float4*)&sF[cur][k][ts << 2];
            float av[8] = {a0.x, a0.y, a0.z, a0.w, a1.x, a1.y, a1.z, a1.w};
            float fv[4] = {f.x, f.y, f.z, f.w};
            #pragma unroll
            for (int i = 0; i < 8; i++)
                #pragma unroll
                for (int j = 0; j < 4; j++)
                    acc[i][j] += av[i] * fv[j];
        }
        if (t < 15) {                       // fill the other buffer
            const int nxt = cur ^ 1;
            const int kk = wk << 2;
            sW[nxt][kk + 0][we] = wr.x;
            sW[nxt][kk + 1][we] = wr.y;
            sW[nxt][kk + 2][we] = wr.z;
            sW[nxt][kk + 3][we] = wr.w;
            *(float4*)&sF[nxt][fk][fs] = fr;
        }
        __syncthreads();
    }

    // split-K epilogue: accumulate raw sums into g_proj via REDG
    #pragma unroll
    for (int i = 0; i < 8; i++) {
        const int e = eBase + (te << 3) + i;
        float* dst = &g_proj[((size_t)(b * EE + e)) * SS + s0 + (ts << 2)];
        #pragma unroll
        for (int j = 0; j < 4; j++)
            atomicAdd(dst + j, acc[i][j]);
    }
}

// ---------------------------------------------------------------------------
// Kernel B: BN+ReLU (on-the-fly) + mask-weighted pooling + 2-layer MLP.
// Grid: 128 blocks = (b in [0,16)) x (ng in [0,8)); each block owns 4 (b,n) rows.
// 512 threads: tid = part*128 + e ; part splits the 256-s reduction 4 ways,
// then becomes the row index for the MLP (4 rows x 128 channels = 512 threads).
// ---------------------------------------------------------------------------
__global__ void __launch_bounds__(512) kernelB(
    const float* __restrict__ conv_b,
    const float* __restrict__ bn_gamma, const float* __restrict__ bn_beta,
    const float* __restrict__ bn_mean,  const float* __restrict__ bn_var,
    const float* __restrict__ w1, const float* __restrict__ b1,
    const float* __restrict__ w2, const float* __restrict__ b2,
    float* __restrict__ out)
{
    const int b  = blockIdx.x >> 3;
    const int ng = blockIdx.x & 7;
    const int n0 = ng * 4;
    const int tid  = threadIdx.x;
    const int e    = tid & 127;
    const int part = tid >> 7;           // 0..3

    __shared__ float mrs[4][SS];         // 4 resized masks (4 KB)
    __shared__ float px[4][4][EE];       // partial sums [part][row][e] (8 KB)
    __shared__ float xs[4][EE];          // obj rows
    __shared__ float hs[4][EE];          // hidden rows
    __shared__ float inv[4];

    for (int i = tid; i < 4 * SS; i += 512)
        mrs[i >> 8][i & 255] = g_mr[((size_t)(b * NN + n0 + (i >> 8))) * SS + (i & 255)];
    if (tid < 4) inv[tid] = g_minv[b * NN + n0 + tid];

    const float sc   = bn_gamma[e] * rsqrtf(bn_var[e] + 1e-5f);
    const float bias = (conv_b[e] - bn_mean[e]) * sc + bn_beta[e];
    __syncthreads();

    // pooling partials: thread (e, part) covers s in [part*64, part*64+64)
    {
        const float* pr = g_proj + ((size_t)(b * EE + e)) * SS + part * 64;
        float a0 = 0.f, a1 = 0.f, a2 = 0.f, a3 = 0.f;
        #pragma unroll 4
        for (int s = 0; s < 64; s += 4) {
            float4 p = *(const float4*)&pr[s];
            p.x = fmaxf(p.x * sc + bias, 0.f);
            p.y = fmaxf(p.y * sc + bias, 0.f);
            p.z = fmaxf(p.z * sc + bias, 0.f);
            p.w = fmaxf(p.w * sc + bias, 0.f);
            const int sg = part * 64 + s;
            float4 m0 = *(const float4*)&mrs[0][sg];
            float4 m1 = *(const float4*)&mrs[1][sg];
            float4 m2 = *(const float4*)&mrs[2][sg];
            float4 m3 = *(const float4*)&mrs[3][sg];
            a0 += p.x * m0.x + p.y * m0.y + p.z * m0.z + p.w * m0.w;
            a1 += p.x * m1.x + p.y * m1.y + p.z * m1.z + p.w * m1.w;
            a2 += p.x * m2.x + p.y * m2.y + p.z * m2.z + p.w * m2.w;
            a3 += p.x * m3.x + p.y * m3.y + p.z * m3.z + p.w * m3.w;
        }
        px[part][0][e] = a0;
        px[part][1][e] = a1;
        px[part][2][e] = a2;
        px[part][3][e] = a3;
    }
    __syncthreads();

    // reduce partials: thread (e, row=part)
    {
        const int rw = part;
        float v = px[0][rw][e] + px[1][rw][e] + px[2][rw][e] + px[3][rw][e];
        xs[rw][e] = v * inv[rw];
    }
    __syncthreads();

    // layer 1: thread (e, row=part)
    {
        const float* wrow = w1 + (size_t)e * EE;
        float a = 0.f;
        #pragma unroll 8
        for (int k = 0; k < EE; k += 4) {
            float4 wv = *(const float4*)&wrow[k];
            float4 xv = *(const float4*)&xs[part][k];
            a += wv.x * xv.x + wv.y * xv.y + wv.z * xv.z + wv.w * xv.w;
        }
        hs[part][e] = fmaxf(a + b1[e], 0.f);
    }
    __syncthreads();

    // layer 2
    {
        const float* wrow = w2 + (size_t)e * EE;
        float a = 0.f;
        #pragma unroll 8
        for (int k = 0; k < EE; k += 4) {
            float4 wv = *(const float4*)&wrow[k];
            float4 xv = *(const float4*)&hs[part][k];
            a += wv.x * xv.x + wv.y * xv.y + wv.z * xv.z + wv.w * xv.w;
        }
        out[((size_t)(b * NN + n0 + part)) * EE + e] = a + b2[e];
    }
}

extern "C" void kernel_launch(void* const* d_in, const int* in_sizes, int n_in,
                              void* d_out, int out_size)
{
    const float* features = (const float*)d_in[0];
    const float* masks    = (const float*)d_in[1];
    const float* conv_w   = (const float*)d_in[2];
    const float* conv_b   = (const float*)d_in[3];
    const float* bn_gamma = (const float*)d_in[4];
    const float* bn_beta  = (const float*)d_in[5];
    const float* bn_mean  = (const float*)d_in[6];
    const float* bn_var   = (const float*)d_in[7];
    const float* w1       = (const float*)d_in[8];
    const float* b1       = (const float*)d_in[9];
    const float* w2       = (const float*)d_in[10];
    const float* b2       = (const float*)d_in[11];
    float* out = (float*)d_out;

    kernelZero<<<128, 1024>>>();
    kernelA<<<1024, 128>>>(features, masks, conv_w);
    kernelB<<<128, 512>>>(conv_b, bn_gamma, bn_beta, bn_mean, bn_var,
                          w1, b1, w2, b2, out);
}